// round 16
// baseline (speedup 1.0000x reference)
#include <cuda_runtime.h>
#include <cuda_bf16.h>
#include <math.h>
#include <stdint.h>

#define INF_ 100000.0f

// ================= scratch (floats) =================
static constexpr size_t OFF_PROJ  = 0;                                 // 512*1152
static constexpr size_t OFF_KEXT  = OFF_PROJ  + (size_t)512*1152;      // 12*512*32
static constexpr size_t OFF_QEXT  = OFF_KEXT  + (size_t)12*512*32;     // 512*12*32
static constexpr size_t OFF_V     = OFF_QEXT  + (size_t)512*12*32;     // 512*192
static constexpr size_t OFF_VPTS  = OFF_V     + (size_t)512*192;       // 512*288
static constexpr size_t OFF_B     = OFF_VPTS  + (size_t)512*288;       // 512*12*512
static constexpr size_t OFF_A     = OFF_B     + (size_t)512*12*512;    // 512*12*512
static constexpr size_t OFF_AINT  = OFF_A     + (size_t)512*12*512;    // bf16 512*3072
static constexpr size_t OFF_WINTP = OFF_AINT  + (size_t)512*3072/2;    // bf16 1152*3072
static constexpr size_t OFF_CINT  = OFF_WINTP + (size_t)1152*3072/2;   // bf16 512*6336
static constexpr size_t OFF_WINTO = OFF_CINT  + (size_t)512*6336/2;    // bf16 1024*6336
static constexpr size_t OFF_BIASA = OFF_WINTO + (size_t)1024*6336/2;   // 1152
static constexpr size_t SCRATCH_TOTAL = OFF_BIASA + 1152;

__device__ __align__(256) float g_scratch[SCRATCH_TOTAL];

#define FMA2(c, a, b) asm("fma.rn.f32x2 %0, %1, %2, %0;" : "+l"(c) : "l"(a), "l"(b))

__device__ __forceinline__ unsigned long long packf2(float lo, float hi) {
    unsigned long long r;
    asm("mov.b64 %0, {%1,%2};" : "=l"(r) : "f"(lo), "f"(hi));
    return r;
}
__device__ __forceinline__ float2 unpackf2(unsigned long long v) {
    float2 r;
    asm("mov.b64 {%0,%1}, %2;" : "=f"(r.x), "=f"(r.y) : "l"(v));
    return r;
}

__device__ __forceinline__ uint32_t smem_u32(const void* p) {
    uint32_t a;
    asm("{ .reg .u64 t; cvta.to.shared.u64 t, %1; cvt.u32.u64 %0, t; }" : "=r"(a) : "l"(p));
    return a;
}

// write one fp32 pair as the 3-u32 interleaved hi/lo pattern (A-side: [hi,lo][hi,hi][lo,hi])
__device__ __forceinline__ void bf16pair_store(uint32_t* d, int p, float a0, float a1) {
    __nv_bfloat16 h0 = __float2bfloat16(a0);
    __nv_bfloat16 l0 = __float2bfloat16(a0 - __bfloat162float(h0));
    __nv_bfloat16 h1 = __float2bfloat16(a1);
    __nv_bfloat16 l1 = __float2bfloat16(a1 - __bfloat162float(h1));
    uint32_t uh0 = __bfloat16_as_ushort(h0), ul0 = __bfloat16_as_ushort(l0);
    uint32_t uh1 = __bfloat16_as_ushort(h1), ul1 = __bfloat16_as_ushort(l1);
    d[3 * p + 0] = uh0 | (ul0 << 16);
    d[3 * p + 1] = uh0 | (uh1 << 16);
    d[3 * p + 2] = ul1 | (uh1 << 16);
}

// ================= prep_all =================
__device__ __forceinline__ void wsplit_body(const float* __restrict__ W,
                                            __nv_bfloat16* __restrict__ dst,
                                            int N, int Kp, int rowoff, int kp, int n) {
    if (n >= N) return;
    float a0 = W[(size_t)(2 * kp) * N + n];
    float a1 = W[(size_t)(2 * kp + 1) * N + n];
    __nv_bfloat16 h0 = __float2bfloat16(a0);
    __nv_bfloat16 l0 = __float2bfloat16(a0 - __bfloat162float(h0));
    __nv_bfloat16 h1 = __float2bfloat16(a1);
    __nv_bfloat16 l1 = __float2bfloat16(a1 - __bfloat162float(h1));
    uint32_t uh0 = __bfloat16_as_ushort(h0), ul0 = __bfloat16_as_ushort(l0);
    uint32_t uh1 = __bfloat16_as_ushort(h1), ul1 = __bfloat16_as_ushort(l1);
    uint32_t* d = (uint32_t*)(dst + (size_t)(rowoff + n) * Kp) + 3 * kp;
    d[0] = uh0 | (uh0 << 16);   // W-side: [hi,hi][lo,hi][hi,lo]
    d[1] = ul0 | (uh1 << 16);
    d[2] = uh1 | (ul1 << 16);
}

__global__ void prep_all(const float* __restrict__ s,
                         const float* __restrict__ Wq,  const float* __restrict__ Wkv,
                         const float* __restrict__ Wqp, const float* __restrict__ Wkvp,
                         const float* __restrict__ Wout,
                         const float* __restrict__ bq,  const float* __restrict__ bkv,
                         const float* __restrict__ bqp, const float* __restrict__ bkvp,
                         __nv_bfloat16* __restrict__ Aint,
                         __nv_bfloat16* __restrict__ WintP,
                         __nv_bfloat16* __restrict__ WintO,
                         float* __restrict__ biasA) {
    int bid = blockIdx.x, t = threadIdx.x;     // 256 threads
    if (bid < 512) {
        const float* sr = s + (size_t)bid * 1024;
        uint32_t* d = (uint32_t*)(Aint + (size_t)bid * 3072);
        #pragma unroll
        for (int u = 0; u < 2; u++) {
            int p = t + u * 256;
            float a0 = sr[2 * p], a1 = sr[2 * p + 1];
            __nv_bfloat16 h0 = __float2bfloat16(a0);
            __nv_bfloat16 l0 = __float2bfloat16(a0 - __bfloat162float(h0));
            __nv_bfloat16 h1 = __float2bfloat16(a1);
            __nv_bfloat16 l1 = __float2bfloat16(a1 - __bfloat162float(h1));
            uint32_t uh0 = __bfloat16_as_ushort(h0), ul0 = __bfloat16_as_ushort(l0);
            uint32_t uh1 = __bfloat16_as_ushort(h1), ul1 = __bfloat16_as_ushort(l1);
            d[3 * p + 0] = uh0 | (ul0 << 16);
            d[3 * p + 1] = uh0 | (uh1 << 16);
            d[3 * p + 2] = ul1 | (uh1 << 16);
        }
    } else if (bid < 1024) {
        wsplit_body(Wq, WintP, 192, 3072, 0, bid - 512, t);
    } else if (bid < 2048) {
        int local = bid - 1024;
        wsplit_body(Wkv, WintP, 384, 3072, 192, local >> 1, ((local & 1) << 8) + t);
    } else if (bid < 2560) {
        wsplit_body(Wqp, WintP, 144, 3072, 576, bid - 2048, t);
    } else if (bid < 3584) {
        int local = bid - 2560;
        wsplit_body(Wkvp, WintP, 432, 3072, 720, local >> 1, ((local & 1) << 8) + t);
    } else if (bid < 7808) {
        int local = bid - 3584;
        wsplit_body(Wout, WintO, 1024, 6336, 0, local >> 2, ((local & 3) << 8) + t);
    } else {
        int idx = (bid - 7808) * 256 + t;
        if (idx < 1152) {
            float v;
            if (idx < 192) v = bq[idx];
            else if (idx < 576) v = bkv[idx - 192];
            else if (idx < 720) v = bqp[idx - 576];
            else v = bkvp[idx - 720];
            biasA[idx] = v;
        }
    }
}

// ================= warp-MMA bf16 GEMM: 256 thr, 64x64 tile, 8 warps (16x32 each) =================
#define ROWP 72
#define BUFB (64 * ROWP * 2)

__global__ void __launch_bounds__(256) mma_gemm(const __nv_bfloat16* __restrict__ A,
                                                const __nv_bfloat16* __restrict__ B,
                                                const float* __restrict__ bias,
                                                float* __restrict__ C,
                                                int Kp, int Nld) {
    __shared__ __align__(16) __nv_bfloat16 sA[2][64][ROWP];
    __shared__ __align__(16) __nv_bfloat16 sB[2][64][ROWP];
    int tid = threadIdx.x, wid = tid >> 5, lane = tid & 31;
    int m0 = blockIdx.y * 64, n0 = blockIdx.x * 64;
    int Mw = (wid >> 1) * 16, Nw = (wid & 1) * 32;

    uint32_t sA_base = smem_u32(&sA[0][0][0]);
    uint32_t sB_base = smem_u32(&sB[0][0][0]);
    uint32_t aoff0 = ((uint32_t)((Mw + (lane & 15)) * ROWP + ((lane >> 4) << 3))) << 1;
    uint32_t boff0 = ((uint32_t)((Nw + (lane & 7)) * ROWP + (lane & 8))) << 1;

    const char* Abase = (const char*)A;
    const char* Bbase = (const char*)B;
    int ntiles = Kp >> 6;

    #pragma unroll
    for (int u = 0; u < 2; u++) {
        int idx = tid + u * 256;
        int row = idx >> 3, c = idx & 7;
        *(uint4*)((char*)&sA[0][0][0] + row * (ROWP * 2) + c * 16) =
            *(const uint4*)(Abase + ((size_t)(m0 + row) * Kp + c * 8) * 2);
        *(uint4*)((char*)&sB[0][0][0] + row * (ROWP * 2) + c * 16) =
            *(const uint4*)(Bbase + ((size_t)(n0 + row) * Kp + c * 8) * 2);
    }
    __syncthreads();

    float acc[4][4] = {};
    for (int t = 0; t < ntiles; t++) {
        int b = t & 1;
        uint4 pa[2], pb[2];
        bool more = (t + 1) < ntiles;
        if (more) {
            #pragma unroll
            for (int u = 0; u < 2; u++) {
                int idx = tid + u * 256;
                int row = idx >> 3, c = idx & 7;
                pa[u] = *(const uint4*)(Abase + ((size_t)(m0 + row) * Kp + (t + 1) * 64 + c * 8) * 2);
                pb[u] = *(const uint4*)(Bbase + ((size_t)(n0 + row) * Kp + (t + 1) * 64 + c * 8) * 2);
            }
        }
        #pragma unroll
        for (int ks = 0; ks < 4; ks++) {
            uint32_t kb = (uint32_t)ks << 5;
            uint32_t af[4], bfr[4][2];
            {
                uint32_t ad = sA_base + b * BUFB + aoff0 + kb;
                asm volatile("ldmatrix.sync.aligned.m8n8.x4.shared.b16 {%0,%1,%2,%3}, [%4];"
                    : "=r"(af[0]), "=r"(af[1]), "=r"(af[2]), "=r"(af[3]) : "r"(ad));
            }
            #pragma unroll
            for (int nt = 0; nt < 4; nt++) {
                uint32_t bd = sB_base + b * BUFB + boff0 + nt * (8 * ROWP * 2) + kb;
                asm volatile("ldmatrix.sync.aligned.m8n8.x2.shared.b16 {%0,%1}, [%2];"
                    : "=r"(bfr[nt][0]), "=r"(bfr[nt][1]) : "r"(bd));
            }
            #pragma unroll
            for (int nt = 0; nt < 4; nt++)
                asm volatile("mma.sync.aligned.m16n8k16.row.col.f32.bf16.bf16.f32 "
                    "{%0,%1,%2,%3}, {%4,%5,%6,%7}, {%8,%9}, {%0,%1,%2,%3};"
                    : "+f"(acc[nt][0]), "+f"(acc[nt][1]), "+f"(acc[nt][2]), "+f"(acc[nt][3])
                    : "r"(af[0]), "r"(af[1]), "r"(af[2]), "r"(af[3]),
                      "r"(bfr[nt][0]), "r"(bfr[nt][1]));
        }
        if (more) {
            __syncthreads();
            #pragma unroll
            for (int u = 0; u < 2; u++) {
                int idx = tid + u * 256;
                int row = idx >> 3, c = idx & 7;
                *(uint4*)((char*)&sA[b ^ 1][0][0] + row * (ROWP * 2) + c * 16) = pa[u];
                *(uint4*)((char*)&sB[b ^ 1][0][0] + row * (ROWP * 2) + c * 16) = pb[u];
            }
            __syncthreads();
        }
    }

    int r = m0 + Mw + (lane >> 2);
    #pragma unroll
    for (int nt = 0; nt < 4; nt++) {
        int col = n0 + Nw + nt * 8 + ((lane & 3) << 1);
        float b0v = bias[col], b1v = bias[col + 1];
        float2 o0 = { acc[nt][0] + b0v, acc[nt][1] + b1v };
        float2 o1 = { acc[nt][2] + b0v, acc[nt][3] + b1v };
        *(float2*)&C[(size_t)r * Nld + col] = o0;
        *(float2*)&C[(size_t)(r + 8) * Nld + col] = o1;
    }
}

// ================= pointify =================
__global__ void pointify(const float* __restrict__ proj,
                         const float* __restrict__ rot,
                         const float* __restrict__ trans,
                         const float* __restrict__ head_w,
                         float* __restrict__ kext, float* __restrict__ qext,
                         float* __restrict__ v, float* __restrict__ vpts) {
    int n = blockIdx.x, t = threadIdx.x;   // 256 threads
    __shared__ float Rs[9], ts[3], qg[144], kg[432], hw_s[12];
    const float* prow = proj + (size_t)n * 1152;
    if (t < 9) Rs[t] = rot[n * 9 + t];
    if (t >= 16 && t < 19) ts[t - 16] = trans[n * 3 + (t - 16)];
    if (t >= 32 && t < 44) {
        float w = head_w[t - 32];
        float sp = (w > 20.f) ? w : log1pf(expf(w));
        hw_s[t - 32] = sp * 0.13608276348795434f;   // sqrt(1/54)
    }
    __syncthreads();
    if (t < 48) {
        float x  = prow[576 + t];
        float y  = prow[576 + 48 + t];
        float zc = prow[576 + 96 + t];
        qg[t * 3 + 0] = Rs[0] * x + Rs[1] * y + Rs[2] * zc + ts[0];
        qg[t * 3 + 1] = Rs[3] * x + Rs[4] * y + Rs[5] * zc + ts[1];
        qg[t * 3 + 2] = Rs[6] * x + Rs[7] * y + Rs[8] * zc + ts[2];
    }
    if (t >= 64 && t < 208) {
        int pf = t - 64;
        float x  = prow[720 + pf];
        float y  = prow[720 + 144 + pf];
        float zc = prow[720 + 288 + pf];
        kg[pf * 3 + 0] = Rs[0] * x + Rs[1] * y + Rs[2] * zc + ts[0];
        kg[pf * 3 + 1] = Rs[3] * x + Rs[4] * y + Rs[5] * zc + ts[1];
        kg[pf * 3 + 2] = Rs[6] * x + Rs[7] * y + Rs[8] * zc + ts[2];
    }
    __syncthreads();
    if (t < 192) {
        int hh = t >> 4, d = t & 15;
        kext[((size_t)hh * 512 + n) * 32 + d] = prow[192 + hh * 32 + d];
        v[(size_t)n * 192 + t]                = prow[192 + hh * 32 + 16 + d];
        qext[((size_t)n * 12 + hh) * 32 + d]  = 0.14433756729740643f * prow[t];
    }
    for (int idx = t; idx < 288; idx += 256) {
        int hh = idx / 24, rem = idx % 24;
        vpts[(size_t)n * 288 + idx] = kg[hh * 36 + 12 + rem];
    }
    if (t < 12) {
        int hh = t; float hw = hw_s[hh];
        float Sk = 0.f, Sq = 0.f;
        float* ke = &kext[((size_t)hh * 512 + n) * 32];
        float* qe = &qext[((size_t)n * 12 + hh) * 32];
        #pragma unroll
        for (int u = 0; u < 12; u++) {
            float kvv = kg[hh * 36 + u];  Sk += kvv * kvv;  ke[16 + u] = kvv;
            float qvv = qg[hh * 12 + u];  Sq += qvv * qvv;  qe[16 + u] = hw * qvv;
        }
        ke[28] = -0.5f * hw * Sk; ke[29] = 1.f; ke[30] = 0.f; ke[31] = 0.f;
        qe[28] = 1.f; qe[29] = -0.5f * hw * Sq; qe[30] = 0.f; qe[31] = 0.f;
    }
}

// ================= bproj128: 128 rows/block, thread-pair per row (d-split), FMA2 =================
__global__ void __launch_bounds__(256) bproj128(const float* __restrict__ z,
                                                const float* __restrict__ Wb,
                                                const float* __restrict__ bb,
                                                float* __restrict__ bmat) {
    extern __shared__ float zs[];                          // [128][132]
    __shared__ __align__(16) float Wb_s[2][12][68];        // 68-pad: rows 16B-aligned
    __shared__ float bb_s[12];
    const float c_b = 0.5773502691896258f;
    int t = threadIdx.x;                    // 256
    size_t r0 = (size_t)blockIdx.x * 128;
    for (int idx = t; idx < 1536; idx += 256) {
        int half = idx / 768, rem = idx - half * 768;
        int h = rem >> 6, d = rem & 63;
        Wb_s[half][h][d] = c_b * Wb[(half * 64 + d) * 12 + h];
    }
    if (t < 12) bb_s[t] = c_b * bb[t];
    #pragma unroll
    for (int u = 0; u < 16; u++) {
        int idx = t + u * 256;
        int row = idx >> 5, c4 = (idx & 31) << 2;
        float4 vv = *(const float4*)&z[(r0 + row) * 128 + c4];
        *(float4*)&zs[row * 132 + c4] = vv;
    }
    __syncthreads();
    int row = t >> 1, half = t & 1;
    const float* zrow = &zs[row * 132 + half * 64];
    unsigned long long acc[12] = {};
    #pragma unroll 4
    for (int d4 = 0; d4 < 16; d4++) {
        float4 zv = *(const float4*)&zrow[d4 << 2];
        unsigned long long zp0 = packf2(zv.x, zv.y);
        unsigned long long zp1 = packf2(zv.z, zv.w);
        #pragma unroll
        for (int h = 0; h < 12; h++) {
            ulonglong2 wv = *(const ulonglong2*)&Wb_s[half][h][d4 << 2];
            FMA2(acc[h], zp0, wv.x);
            FMA2(acc[h], zp1, wv.y);
        }
    }
    size_t rowg = r0 + row;
    int i = (int)(rowg >> 9), j = (int)(rowg & 511);
    #pragma unroll
    for (int h = 0; h < 12; h++) {
        float2 p = unpackf2(acc[h]);
        float s = p.x + p.y;
        s += __shfl_xor_sync(0xffffffffu, s, 1);
        if (half == 0)
            bmat[((size_t)i * 12 + h) * 512 + j] = s + bb_s[h];
    }
}

// ================= logits (rank-30) + mask + softmax, 16 rows/block =================
__global__ void logits_softmax(const float* __restrict__ qext,
                               const float* __restrict__ kext,
                               const float* __restrict__ bmat,
                               const float* __restrict__ mask,
                               float* __restrict__ a) {
    int i0 = blockIdx.x * 16, h = blockIdx.y;   // grid (32, 12)
    int t = threadIdx.x;     // 256
    int w = t >> 5, l = t & 31;
    __shared__ __align__(16) float qe[16][32];
    __shared__ __align__(16) float ke[32][65];
    __shared__ __align__(16) float b_s[16][64];
    __shared__ float ms[512], mi_s[16];
    if (t < 128) {
        int r = t >> 3, d4 = (t & 7) << 2;
        *(float4*)&qe[r][d4] = *(const float4*)&qext[((size_t)(i0 + r) * 12 + h) * 32 + d4];
    }
    for (int idx = t; idx < 512; idx += 256) ms[idx] = mask[idx];
    if (t < 16) mi_s[t] = mask[i0 + t];
    float rmax[2] = {-3.4e38f, -3.4e38f};
    for (int jt = 0; jt < 8; jt++) {
        int j0 = jt * 64;
        __syncthreads();
        #pragma unroll
        for (int idx = t; idx < 512; idx += 256) {
            int jr = idx >> 3, d4 = (idx & 7) << 2;
            float4 kv = *(const float4*)&kext[((size_t)h * 512 + j0 + jr) * 32 + d4];
            ke[d4 + 0][jr] = kv.x; ke[d4 + 1][jr] = kv.y;
            ke[d4 + 2][jr] = kv.z; ke[d4 + 3][jr] = kv.w;
        }
        {
            int r = t >> 4, c4 = (t & 15) << 2;
            *(float4*)&b_s[r][c4] =
                *(const float4*)&bmat[((size_t)(i0 + r) * 12 + h) * 512 + j0 + c4];
        }
        __syncthreads();
        float acc[2][2] = {};
        #pragma unroll 5
        for (int d = 0; d < 30; d++) {
            float k0 = ke[d][l], k1 = ke[d][l + 32];
            #pragma unroll
            for (int rr = 0; rr < 2; rr++) {
                float qv = qe[(w << 1) + rr][d];
                acc[rr][0] += qv * k0;
                acc[rr][1] += qv * k1;
            }
        }
        float mj0 = ms[j0 + l], mj1 = ms[j0 + l + 32];
        #pragma unroll
        for (int rr = 0; rr < 2; rr++) {
            int r = (w << 1) + rr;
            float mi = mi_s[r];
            float lg0 = acc[rr][0] + b_s[r][l]      + INF_ * fmaf(mi, mj0, -1.f);
            float lg1 = acc[rr][1] + b_s[r][l + 32] + INF_ * fmaf(mi, mj1, -1.f);
            float* arow = a + ((size_t)(i0 + r) * 12 + h) * 512 + j0;
            arow[l] = lg0;
            arow[l + 32] = lg1;
            rmax[rr] = fmaxf(rmax[rr], fmaxf(lg0, lg1));
        }
    }
    #pragma unroll
    for (int off = 16; off > 0; off >>= 1)
        #pragma unroll
        for (int rr = 0; rr < 2; rr++)
            rmax[rr] = fmaxf(rmax[rr], __shfl_xor_sync(0xffffffffu, rmax[rr], off));
    #pragma unroll
    for (int rr = 0; rr < 2; rr++) {
        float* arow = a + ((size_t)(i0 + (w << 1) + rr) * 12 + h) * 512;
        float mx = rmax[rr];
        float sum = 0.f;
        #pragma unroll
        for (int c = l; c < 512; c += 32) sum += __expf(arow[c] - mx);
        #pragma unroll
        for (int off = 16; off > 0; off >>= 1)
            sum += __shfl_xor_sync(0xffffffffu, sum, off);
        float inv = 1.f / sum;
        #pragma unroll
        for (int c = l; c < 512; c += 32) arow[c] = __expf(arow[c] - mx) * inv;
    }
}

// ================= att_out -> writes bf16 triplets of cols [0,576) into Cint =================
__global__ void att_out(const float* __restrict__ a,
                        const float* __restrict__ v,
                        const float* __restrict__ vpts,
                        const float* __restrict__ rot,
                        const float* __restrict__ trans,
                        __nv_bfloat16* __restrict__ Cint) {
    int i0 = blockIdx.x * 4;
    int t = threadIdx.x;    // 480
    __shared__ float a_s[4][768];
    __shared__ float opts[4][288];
    __shared__ float cvals[4][576];
    __shared__ float Rs[4][9], ts[4][3];
    if (t < 36) Rs[t / 9][t % 9] = rot[(i0 + t / 9) * 9 + t % 9];
    if (t >= 64 && t < 76) {
        int r = (t - 64) / 3, cpt = (t - 64) % 3;
        ts[r][cpt] = trans[(i0 + r) * 3 + cpt];
    }
    float acc[4] = {0.f, 0.f, 0.f, 0.f};
    int h = (t < 192) ? (t >> 4) : ((t - 192) / 24);
    const float* src = (t < 192) ? (v + t) : (vpts + (t - 192));
    int stride = (t < 192) ? 192 : 288;
    for (int j0 = 0; j0 < 512; j0 += 64) {
        for (int idx = t; idx < 3072; idx += 480) {
            int r = idx / 768;
            int rem = idx - r * 768;
            int hh = rem >> 6, jj = rem & 63;
            a_s[r][rem] = a[((size_t)(i0 + r) * 12 + hh) * 512 + j0 + jj];
        }
        __syncthreads();
        const float* sp = src + (size_t)j0 * stride;
        const float* as0 = &a_s[0][h * 64];
        #pragma unroll 4
        for (int jj = 0; jj < 64; jj++) {
            float val = sp[(size_t)jj * stride];
            acc[0] += as0[jj]        * val;
            acc[1] += as0[768 + jj]  * val;
            acc[2] += as0[1536 + jj] * val;
            acc[3] += as0[2304 + jj] * val;
        }
        __syncthreads();
    }
    if (t >= 192) {
        #pragma unroll
        for (int r = 0; r < 4; r++) opts[r][t - 192] = acc[r];
    }
    __syncthreads();
    #pragma unroll
    for (int r = 0; r < 4; r++) {
        if (t < 192) cvals[r][t] = acc[r];
        if (t < 96) {
            int hh = t >> 3, p = t & 7;
            int base = hh * 24 + p * 3;
            float gx = opts[r][base]     - ts[r][0];
            float gy = opts[r][base + 1] - ts[r][1];
            float gz = opts[r][base + 2] - ts[r][2];
            float lx = Rs[r][0] * gx + Rs[r][3] * gy + Rs[r][6] * gz;
            float ly = Rs[r][1] * gx + Rs[r][4] * gy + Rs[r][7] * gz;
            float lz = Rs[r][2] * gx + Rs[r][5] * gy + Rs[r][8] * gz;
            cvals[r][192 + t] = lx;
            cvals[r][288 + t] = ly;
            cvals[r][384 + t] = lz;
            cvals[r][480 + t] = sqrtf(lx * lx + ly * ly + lz * lz + 1e-8f);
        }
    }
    __syncthreads();
    for (int idx = t; idx < 4 * 288; idx += 480) {
        int r = idx / 288, p = idx - r * 288;
        uint32_t* d = (uint32_t*)(Cint + (size_t)(i0 + r) * 6336);
        bf16pair_store(d, p, cvals[r][2 * p], cvals[r][2 * p + 1]);
    }
}

// ================= opair: 2 j-groups x 128 cols, FMA2 -> bf16 triplets cols [576,2112) =================
__global__ void __launch_bounds__(256) opair(const float* __restrict__ a,
                                             const float* __restrict__ z,
                                             __nv_bfloat16* __restrict__ Cint) {
    int i = blockIdx.x;
    int t = threadIdx.x;           // 256
    int jg = t >> 7, c = t & 127;  // j-group, column
    __shared__ __align__(16) float a_s[2][768];
    __shared__ float red[12][128];
    unsigned long long acc2[12] = {};
    for (int jt = 0; jt < 4; jt++) {
        int j0 = jg * 256 + jt * 64;
        for (int idx = c; idx < 768; idx += 128) {
            int hh = idx >> 6, jj = idx & 63;
            a_s[jg][idx] = a[((size_t)i * 12 + hh) * 512 + j0 + jj];
        }
        __syncthreads();
        const float* zp = z + ((size_t)i * 512 + j0) * 128 + c;
        #pragma unroll
        for (int jj4 = 0; jj4 < 16; jj4++) {
            int jj = jj4 * 4;
            float z0 = zp[(size_t)(jj + 0) * 128];
            float z1 = zp[(size_t)(jj + 1) * 128];
            float z2 = zp[(size_t)(jj + 2) * 128];
            float z3 = zp[(size_t)(jj + 3) * 128];
            unsigned long long pz01 = packf2(z0, z1);
            unsigned long long pz23 = packf2(z2, z3);
            #pragma unroll
            for (int hh = 0; hh < 12; hh++) {
                ulonglong2 av = *(const ulonglong2*)&a_s[jg][hh * 64 + jj];
                FMA2(acc2[hh], av.x, pz01);
                FMA2(acc2[hh], av.y, pz23);
            }
        }
        __syncthreads();
    }
    float acc[12];
    #pragma unroll
    for (int hh = 0; hh < 12; hh++) {
        float2 p = unpackf2(acc2[hh]);
        acc[hh] = p.x + p.y;
    }
    if (jg == 1) {
        #pragma unroll
        for (int hh = 0; hh < 12; hh++) red[hh][c] = acc[hh];
    }
    __syncthreads();
    if (jg == 0) {
        uint32_t* d = (uint32_t*)(Cint + (size_t)i * 6336);
        #pragma unroll
        for (int hh = 0; hh < 12; hh++) {
            float tot = acc[hh] + red[hh][c];
            float other = __shfl_xor_sync(0xffffffffu, tot, 1);
            if (!(c & 1)) {
                int p = 288 + hh * 64 + (c >> 1);
                bf16pair_store(d, p, tot, other);
            }
        }
    }
}

// ================= launch =================
extern "C" void kernel_launch(void* const* d_in, const int* in_sizes, int n_in,
                              void* d_out, int out_size) {
    const float* s      = (const float*)d_in[0];
    const float* z      = (const float*)d_in[1];
    const float* rot    = (const float*)d_in[2];
    const float* trans  = (const float*)d_in[3];
    const float* mask   = (const float*)d_in[4];
    const float* Wq     = (const float*)d_in[5];
    const float* bq     = (const float*)d_in[6];
    const float* Wkv    = (const float*)d_in[7];
    const float* bkv    = (const float*)d_in[8];
    const float* Wqp    = (const float*)d_in[9];
    const float* bqp    = (const float*)d_in[10];
    const float* Wkvp   = (const float*)d_in[11];
    const float* bkvp   = (const float*)d_in[12];
    const float* Wb     = (const float*)d_in[13];
    const float* bb     = (const float*)d_in[14];
    const float* head_w = (const float*)d_in[15];
    const float* Wout   = (const float*)d_in[16];
    const float* bout   = (const float*)d_in[17];
    float* out = (float*)d_out;

    float* base = nullptr;
    cudaGetSymbolAddress((void**)&base, g_scratch);
    float* proj  = base + OFF_PROJ;
    float* kext  = base + OFF_KEXT;
    float* qext  = base + OFF_QEXT;
    float* v     = base + OFF_V;
    float* vpts  = base + OFF_VPTS;
    float* bmat  = base + OFF_B;
    float* amat  = base + OFF_A;
    __nv_bfloat16* Aint  = (__nv_bfloat16*)(base + OFF_AINT);
    __nv_bfloat16* WintP = (__nv_bfloat16*)(base + OFF_WINTP);
    __nv_bfloat16* Cint  = (__nv_bfloat16*)(base + OFF_CINT);
    __nv_bfloat16* WintO = (__nv_bfloat16*)(base + OFF_WINTO);
    float* biasA = base + OFF_BIASA;

    static int attr_set = 0;
    if (!attr_set) {
        cudaFuncSetAttribute(bproj128, cudaFuncAttributeMaxDynamicSharedMemorySize,
                             128 * 132 * 4);
        attr_set = 1;
    }

    prep_all<<<7813, 256>>>(s, Wq, Wkv, Wqp, Wkvp, Wout, bq, bkv, bqp, bkvp,
                            Aint, WintP, WintO, biasA);

    // fused projection GEMM: [512,1152] = s @ [Wq|Wkv|Wqp|Wkvp]
    mma_gemm<<<dim3(18, 8), 256>>>(Aint, WintP, biasA, proj, 3072, 1152);

    pointify<<<512, 256>>>(proj, rot, trans, head_w, kext, qext, v, vpts);
    bproj128<<<2048, 256, 128 * 132 * 4>>>(z, Wb, bb, bmat);
    logits_softmax<<<dim3(32, 12), 256>>>(qext, kext, bmat, mask, amat);
    att_out<<<128, 480>>>(amat, v, vpts, rot, trans, Cint);
    opair<<<512, 256>>>(amat, z, Cint);

    // output GEMM: [512,1024] = cat @ Wout (cat already split into Cint)
    mma_gemm<<<dim3(16, 8), 256>>>(Cint, WintO, bout, out, 6336, 1024);
}